// round 2
// baseline (speedup 1.0000x reference)
#include <cuda_runtime.h>

// ---------------------------------------------------------------------------
// Fully fused MLP-Mixer, round 2: 512 threads/CTA (16 warps), E=1 element per
// warp -> 16 elements/CTA, regs/thread <= 128 so the full 64K register file
// supports 16 warps/SM (4/SMSP) for latency hiding. Weights staged in SMEM
// ([256][32] and transposed [256][36], w2 pre-scaled by 1/6), h tiles [32][33].
// All inner products are packed fma.rn.f32x2.
// ---------------------------------------------------------------------------

#define MIX_EPS 1e-5f

// ---- SMEM layout (in floats) ----
#define OFF_W11   0        // 8192  (also fc0_w / fc1_w)
#define OFF_W12T  8192     // 256*36 = 9216
#define OFF_W21   17408    // 8192  (also fcout_w)
#define OFF_W22T  25600    // 9216
#define OFF_B11   34816    // 256   (also fc0_b / fc1_b)
#define OFF_B12   35072    // 32    (also fcout_b)
#define OFF_B21   35104    // 256
#define OFF_B22   35360    // 32
#define OFF_LN1G  35392
#define OFF_LN1B  35424
#define OFF_LN2G  35456
#define OFF_LN2B  35488
#define OFF_H     35520    // 16 elems * 1056
#define OFF_STATS 52416    // 16 elems * 64
#define SMEM_FLOATS 53440  // 213760 bytes

__device__ __forceinline__ float2 ffma2(float2 a, float2 b, float2 c) {
    unsigned long long au = *reinterpret_cast<unsigned long long*>(&a);
    unsigned long long bu = *reinterpret_cast<unsigned long long*>(&b);
    unsigned long long cu = *reinterpret_cast<unsigned long long*>(&c);
    unsigned long long du;
    asm("fma.rn.f32x2 %0, %1, %2, %3;" : "=l"(du) : "l"(au), "l"(bu), "l"(cu));
    return *reinterpret_cast<float2*>(&du);
}

__device__ __forceinline__ float2 fadd2(float2 a, float2 b) {
    unsigned long long au = *reinterpret_cast<unsigned long long*>(&a);
    unsigned long long bu = *reinterpret_cast<unsigned long long*>(&b);
    unsigned long long du;
    asm("add.rn.f32x2 %0, %1, %2;" : "=l"(du) : "l"(au), "l"(bu));
    return *reinterpret_cast<float2*>(&du);
}

// One mixing branch on the single element owned by this warp (E=1).
// TOKEN=true : LN stats per row -> scratch, lane then works on its column.
// TOKEN=false: lane works on its own row (fully lane-local).
// NOTE: sW2T rows are pre-scaled by 1/6, so hswish here omits the 1/6.
template <bool TOKEN>
__device__ __forceinline__ void mix_branch(
    float* h,
    const float* sW1, const float* sW2T,
    const float* sB1, const float* sB2,
    const float* sG, const float* sBb,
    float* st, int lane)
{
    // ---- LN stats over own row (lane = row) ----
    float s = 0.f, q = 0.f;
    #pragma unroll
    for (int j = 0; j < 32; j++) {
        float v = h[lane * 33 + j]; s += v; q += v * v;
    }
    float m = s * 0.03125f;
    float r = rsqrtf(fmaxf(q * 0.03125f - m * m, 0.f) + MIX_EPS);

    float2 l[16];
    if (TOKEN) {
        st[lane] = m; st[32 + lane] = r;
        __syncwarp();
        // lane = column j; normalize column entries with per-row stats
        float gj = sG[lane], bj = sBb[lane];
        #pragma unroll
        for (int t = 0; t < 16; t++) {
            int k0 = 2 * t, k1 = 2 * t + 1;
            float mA = st[k0], rA = st[32 + k0];
            float mB = st[k1], rB = st[32 + k1];
            l[t] = make_float2((h[k0 * 33 + lane] - mA) * rA * gj + bj,
                               (h[k1 * 33 + lane] - mB) * rB * gj + bj);
        }
    } else {
        #pragma unroll
        for (int t = 0; t < 16; t++) {
            int j0 = 2 * t, j1 = 2 * t + 1;
            l[t] = make_float2((h[lane * 33 + j0] - m) * r * sG[j0] + sBb[j0],
                               (h[lane * 33 + j1] - m) * r * sG[j1] + sBb[j1]);
        }
    }

    // out accumulators start at second-layer bias
    float2 out[16];
    #pragma unroll
    for (int t = 0; t < 16; t++)
        out[t] = *reinterpret_cast<const float2*>(sB2 + 2 * t);

    // hidden loop over DIM=256
    for (int d = 0; d < 256; d++) {
        const float4* w1q = reinterpret_cast<const float4*>(sW1 + d * 32);
        float2 a  = make_float2(0.f, 0.f);
        float2 ab = make_float2(0.f, 0.f);
        #pragma unroll
        for (int qq = 0; qq < 8; qq++) {
            float4 w = w1q[qq];
            a  = ffma2(l[2 * qq],     make_float2(w.x, w.y), a);
            ab = ffma2(l[2 * qq + 1], make_float2(w.z, w.w), ab);
        }
        float2 sv = fadd2(a, ab);
        float v  = sv.x + sv.y + sB1[d];
        float cl = fminf(fmaxf(v + 3.0f, 0.0f), 6.0f);
        float hs = v * cl;                       // 1/6 folded into sW2T
        float2 hp = make_float2(hs, hs);
        const float4* w2q = reinterpret_cast<const float4*>(sW2T + d * 36);
        #pragma unroll
        for (int qq = 0; qq < 8; qq++) {
            float4 w = w2q[qq];
            out[2 * qq]     = ffma2(hp, make_float2(w.x, w.y), out[2 * qq]);
            out[2 * qq + 1] = ffma2(hp, make_float2(w.z, w.w), out[2 * qq + 1]);
        }
    }

    // residual add back into h
    if (TOKEN) {
        #pragma unroll
        for (int t = 0; t < 16; t++) {
            h[(2 * t) * 33 + lane]     += out[t].x;
            h[(2 * t + 1) * 33 + lane] += out[t].y;
        }
    } else {
        #pragma unroll
        for (int t = 0; t < 16; t++) {
            h[lane * 33 + 2 * t]     += out[t].x;
            h[lane * 33 + 2 * t + 1] += out[t].y;
        }
    }
    __syncwarp();
}

extern __shared__ float smem[];

__global__ __launch_bounds__(512, 1)
void mixer_kernel(
    const float* __restrict__ x,
    const float* __restrict__ conv_w, const float* __restrict__ conv_b,
    const float* __restrict__ fc0_w,  const float* __restrict__ fc0_b,
    const float* __restrict__ ln1_g,  const float* __restrict__ ln1_b,
    const float* __restrict__ w11,    const float* __restrict__ b11,
    const float* __restrict__ w12,    const float* __restrict__ b12,
    const float* __restrict__ ln2_g,  const float* __restrict__ ln2_b,
    const float* __restrict__ w21,    const float* __restrict__ b21,
    const float* __restrict__ w22,    const float* __restrict__ b22,
    const float* __restrict__ fc1_w,  const float* __restrict__ fc1_b,
    const float* __restrict__ fcout_w,const float* __restrict__ fcout_b,
    float* __restrict__ out, int B)
{
    const int tid  = threadIdx.x;
    const int lane = tid & 31;
    const int wid  = tid >> 5;          // 0..15, one element per warp

    float* sW11  = smem + OFF_W11;
    float* sW12T = smem + OFF_W12T;
    float* sW21  = smem + OFF_W21;
    float* sW22T = smem + OFF_W22T;
    float* sB11  = smem + OFF_B11;
    float* sB12  = smem + OFF_B12;
    float* sB21  = smem + OFF_B21;
    float* sB22  = smem + OFF_B22;
    float* sLn1g = smem + OFF_LN1G;
    float* sLn1b = smem + OFF_LN1B;
    float* sLn2g = smem + OFF_LN2G;
    float* sLn2b = smem + OFF_LN2B;
    float* sH    = smem + OFF_H;
    float* sStats= smem + OFF_STATS;

    const int eb  = blockIdx.x * 16 + wid;
    const bool act = (eb < B);
    float* h  = sH + wid * 1056;
    float* st = sStats + wid * 64;

    // ---- stage fc0 weights, then preprocess (conv1x1 + fc0) ----
    for (int i = tid; i < 1024; i += 512) sW11[i] = fc0_w[i];
    if (tid < 32) sB11[tid] = fc0_b[tid];
    __syncthreads();

    if (act) {
        const float cw0 = conv_w[0], cw1 = conv_w[1], cw2 = conv_w[2];
        const float cb  = conv_b[0];
        const float* xb = x + (size_t)eb * 3072 + lane * 32;
        float2 gp[16];
        #pragma unroll
        for (int qq = 0; qq < 8; qq++) {
            float4 v0 = *reinterpret_cast<const float4*>(xb + qq * 4);
            float4 v1 = *reinterpret_cast<const float4*>(xb + 1024 + qq * 4);
            float4 v2 = *reinterpret_cast<const float4*>(xb + 2048 + qq * 4);
            float g0 = cw0 * v0.x + cw1 * v1.x + cw2 * v2.x + cb;
            float g1 = cw0 * v0.y + cw1 * v1.y + cw2 * v2.y + cb;
            float g2 = cw0 * v0.z + cw1 * v1.z + cw2 * v2.z + cb;
            float g3 = cw0 * v0.w + cw1 * v1.w + cw2 * v2.w + cb;
            gp[2 * qq]     = make_float2(g0, g1);
            gp[2 * qq + 1] = make_float2(g2, g3);
        }
        for (int j = 0; j < 32; j++) {
            const float4* wq = reinterpret_cast<const float4*>(sW11 + j * 32);
            float2 acc  = make_float2(0.f, 0.f);
            float2 accb = make_float2(0.f, 0.f);
            #pragma unroll
            for (int qq = 0; qq < 8; qq++) {
                float4 w = wq[qq];
                acc  = ffma2(gp[2 * qq],     make_float2(w.x, w.y), acc);
                accb = ffma2(gp[2 * qq + 1], make_float2(w.z, w.w), accb);
            }
            float2 sv = fadd2(acc, accb);
            h[lane * 33 + j] = sv.x + sv.y + sB11[j];
        }
    }
    __syncthreads();

    // ---- 8 layers x 2 repeats ----
    for (int l = 0; l < 8; l++) {
        // stage this layer's weights (w12/w22 transposed to [256][36], /6)
        {
            const float4* s1 = reinterpret_cast<const float4*>(w11 + l * 8192);
            float4* d1 = reinterpret_cast<float4*>(sW11);
            for (int i = tid; i < 2048; i += 512) d1[i] = s1[i];
            const float4* s2 = reinterpret_cast<const float4*>(w21 + l * 8192);
            float4* d2 = reinterpret_cast<float4*>(sW21);
            for (int i = tid; i < 2048; i += 512) d2[i] = s2[i];
            const float* g12 = w12 + l * 8192;
            for (int i = tid; i < 8192; i += 512) {
                int d = i & 255, k = i >> 8;
                sW12T[d * 36 + k] = g12[i] * (1.0f / 6.0f);
            }
            const float* g22 = w22 + l * 8192;
            for (int i = tid; i < 8192; i += 512) {
                int d = i & 255, k = i >> 8;
                sW22T[d * 36 + k] = g22[i] * (1.0f / 6.0f);
            }
            if (tid < 256) { sB11[tid] = b11[l * 256 + tid]; sB21[tid] = b21[l * 256 + tid]; }
            if (tid < 32) {
                sB12[tid]  = b12[l * 32 + tid];
                sB22[tid]  = b22[l * 32 + tid];
                sLn1g[tid] = ln1_g[l * 32 + tid];
                sLn1b[tid] = ln1_b[l * 32 + tid];
                sLn2g[tid] = ln2_g[l * 32 + tid];
                sLn2b[tid] = ln2_b[l * 32 + tid];
            }
        }
        __syncthreads();

        for (int rep = 0; rep < 2; rep++) {
            mix_branch<true >(h, sW11, sW12T, sB11, sB12, sLn1g, sLn1b, st, lane);
            mix_branch<false>(h, sW21, sW22T, sB21, sB22, sLn2g, sLn2b, st, lane);
        }
        __syncthreads();
    }

    // ---- head: fc1 + hardswish + avgpool(32) + fcout ----
    {
        const float4* s1 = reinterpret_cast<const float4*>(fc1_w);
        float4* d1 = reinterpret_cast<float4*>(sW11);
        for (int i = tid; i < 1024; i += 512) d1[i] = s1[i];
        for (int i = tid; i < 1280; i += 512) sW21[i] = fcout_w[i];
        if (tid < 128) sB11[tid] = fc1_b[tid];
        if (tid < 10)  sB12[tid] = fcout_b[tid];
    }
    __syncthreads();

    if (act) {
        float2 ap[16];
        #pragma unroll
        for (int t = 0; t < 16; t++)
            ap[t] = make_float2(h[lane * 33 + 2 * t], h[lane * 33 + 2 * t + 1]);
        float pool[4] = {0.f, 0.f, 0.f, 0.f};
        for (int d = 0; d < 128; d++) {
            const float4* wq = reinterpret_cast<const float4*>(sW11 + d * 32);
            float2 acc  = make_float2(0.f, 0.f);
            float2 accb = make_float2(0.f, 0.f);
            #pragma unroll
            for (int qq = 0; qq < 8; qq++) {
                float4 w = wq[qq];
                acc  = ffma2(ap[2 * qq],     make_float2(w.x, w.y), acc);
                accb = ffma2(ap[2 * qq + 1], make_float2(w.z, w.w), accb);
            }
            float2 sv = fadd2(acc, accb);
            float v = sv.x + sv.y + sB11[d];
            float y = v * fminf(fmaxf(v + 3.0f, 0.0f), 6.0f) * (1.0f / 6.0f);
            pool[d >> 5] += y;
        }
        #pragma unroll
        for (int p = 0; p < 4; p++) pool[p] *= (1.0f / 32.0f);
        #pragma unroll
        for (int o = 0; o < 10; o++) {
            float4 wv = *reinterpret_cast<const float4*>(sW21 + o * 128 + lane * 4);
            float v = pool[0] * wv.x + pool[1] * wv.y + pool[2] * wv.z + pool[3] * wv.w;
            #pragma unroll
            for (int sft = 16; sft > 0; sft >>= 1)
                v += __shfl_xor_sync(0xffffffffu, v, sft);
            if (lane == 0) out[(size_t)eb * 10 + o] = v + sB12[o];
        }
    }
}

extern "C" void kernel_launch(void* const* d_in, const int* in_sizes, int n_in,
                              void* d_out, int out_size) {
    const float* x       = (const float*)d_in[0];
    const float* conv_w  = (const float*)d_in[1];
    const float* conv_b  = (const float*)d_in[2];
    const float* fc0_w   = (const float*)d_in[3];
    const float* fc0_b   = (const float*)d_in[4];
    const float* ln1_g   = (const float*)d_in[5];
    const float* ln1_b   = (const float*)d_in[6];
    const float* w11     = (const float*)d_in[7];
    const float* b11     = (const float*)d_in[8];
    const float* w12     = (const float*)d_in[9];
    const float* b12     = (const float*)d_in[10];
    const float* ln2_g   = (const float*)d_in[11];
    const float* ln2_b   = (const float*)d_in[12];
    const float* w21     = (const float*)d_in[13];
    const float* b21     = (const float*)d_in[14];
    const float* w22     = (const float*)d_in[15];
    const float* b22     = (const float*)d_in[16];
    const float* fc1_w   = (const float*)d_in[17];
    const float* fc1_b   = (const float*)d_in[18];
    const float* fcout_w = (const float*)d_in[19];
    const float* fcout_b = (const float*)d_in[20];
    float* out = (float*)d_out;

    const int B = in_sizes[0] / 3072;   // 3*32*32 floats per element
    const int blocks = (B + 15) / 16;
    const size_t smem_bytes = (size_t)SMEM_FLOATS * sizeof(float);

    cudaFuncSetAttribute(mixer_kernel,
                         cudaFuncAttributeMaxDynamicSharedMemorySize,
                         (int)smem_bytes);
    mixer_kernel<<<blocks, 512, smem_bytes>>>(
        x, conv_w, conv_b, fc0_w, fc0_b, ln1_g, ln1_b,
        w11, b11, w12, b12, ln2_g, ln2_b, w21, b21, w22, b22,
        fc1_w, fc1_b, fcout_w, fcout_b, out, B);
}

// round 3
// speedup vs baseline: 1.4155x; 1.4155x over previous
#include <cuda_runtime.h>

// ---------------------------------------------------------------------------
// Fully fused MLP-Mixer, round 3: back to E=2 (256 thr, 8 warps, 16 elems/CTA)
// which sits at the simultaneous FMA+LDS saturation point, plus software
// pipelining: d-loop unrolled by 2 (8 independent gemm1 chains, 4 independent
// horizontal chains), bias folded into accumulator init, 1/6 folded into the
// staged w2T. All inner products are packed fma.rn.f32x2.
// ---------------------------------------------------------------------------

#define MIX_EPS 1e-5f

// ---- SMEM layout (in floats) ----
#define OFF_W11   0        // 8192  (also fc0_w / fc1_w)
#define OFF_W12T  8192     // 256*36 = 9216
#define OFF_W21   17408    // 8192  (also fcout_w)
#define OFF_W22T  25600    // 9216
#define OFF_B11   34816    // 256   (also fc0_b / fc1_b)
#define OFF_B12   35072    // 32    (also fcout_b)
#define OFF_B21   35104    // 256
#define OFF_B22   35360    // 32
#define OFF_LN1G  35392
#define OFF_LN1B  35424
#define OFF_LN2G  35456
#define OFF_LN2B  35488
#define OFF_H     35520    // 16 elems * 1056
#define OFF_STATS 52416    // 8 warps * 2 elems * 64
#define SMEM_FLOATS 53440  // 213760 bytes

__device__ __forceinline__ float2 ffma2(float2 a, float2 b, float2 c) {
    unsigned long long au = *reinterpret_cast<unsigned long long*>(&a);
    unsigned long long bu = *reinterpret_cast<unsigned long long*>(&b);
    unsigned long long cu = *reinterpret_cast<unsigned long long*>(&c);
    unsigned long long du;
    asm("fma.rn.f32x2 %0, %1, %2, %3;" : "=l"(du) : "l"(au), "l"(bu), "l"(cu));
    return *reinterpret_cast<float2*>(&du);
}

__device__ __forceinline__ float2 fadd2(float2 a, float2 b) {
    unsigned long long au = *reinterpret_cast<unsigned long long*>(&a);
    unsigned long long bu = *reinterpret_cast<unsigned long long*>(&b);
    unsigned long long du;
    asm("add.rn.f32x2 %0, %1, %2;" : "=l"(du) : "l"(au), "l"(bu));
    return *reinterpret_cast<float2*>(&du);
}

// One mixing branch on two elements owned by this warp (E=2), d-loop unrolled 2.
// NOTE: sW2T rows are pre-scaled by 1/6, so hswish omits the 1/6 here.
template <bool TOKEN>
__device__ __forceinline__ void mix_branch(
    float* h0, float* h1,
    const float* sW1, const float* sW2T,
    const float* sB1, const float* sB2,
    const float* sG, const float* sBb,
    float* st0, float* st1, int lane)
{
    float2 l0[16], l1[16];

    if (TOKEN) {
        float s0 = 0.f, q0 = 0.f, s1 = 0.f, q1 = 0.f;
        #pragma unroll
        for (int j = 0; j < 32; j++) {
            float v = h0[lane * 33 + j]; s0 += v; q0 += v * v;
            float w = h1[lane * 33 + j]; s1 += w; q1 += w * w;
        }
        float m0 = s0 * 0.03125f, m1 = s1 * 0.03125f;
        float r0 = rsqrtf(fmaxf(q0 * 0.03125f - m0 * m0, 0.f) + MIX_EPS);
        float r1 = rsqrtf(fmaxf(q1 * 0.03125f - m1 * m1, 0.f) + MIX_EPS);
        st0[lane] = m0; st0[32 + lane] = r0;
        st1[lane] = m1; st1[32 + lane] = r1;
        __syncwarp();
        float gj = sG[lane], bj = sBb[lane];
        #pragma unroll
        for (int t = 0; t < 16; t++) {
            int k0 = 2 * t, k1 = 2 * t + 1;
            float mA = st0[k0], rA = st0[32 + k0];
            float mB = st0[k1], rB = st0[32 + k1];
            l0[t] = make_float2((h0[k0 * 33 + lane] - mA) * rA * gj + bj,
                                (h0[k1 * 33 + lane] - mB) * rB * gj + bj);
            float mC = st1[k0], rC = st1[32 + k0];
            float mD = st1[k1], rD = st1[32 + k1];
            l1[t] = make_float2((h1[k0 * 33 + lane] - mC) * rC * gj + bj,
                                (h1[k1 * 33 + lane] - mD) * rD * gj + bj);
        }
    } else {
        float s0 = 0.f, q0 = 0.f, s1 = 0.f, q1 = 0.f;
        #pragma unroll
        for (int j = 0; j < 32; j++) {
            float v = h0[lane * 33 + j]; s0 += v; q0 += v * v;
            float w = h1[lane * 33 + j]; s1 += w; q1 += w * w;
        }
        float m0 = s0 * 0.03125f, m1 = s1 * 0.03125f;
        float r0 = rsqrtf(fmaxf(q0 * 0.03125f - m0 * m0, 0.f) + MIX_EPS);
        float r1 = rsqrtf(fmaxf(q1 * 0.03125f - m1 * m1, 0.f) + MIX_EPS);
        #pragma unroll
        for (int t = 0; t < 16; t++) {
            int j0 = 2 * t, j1 = 2 * t + 1;
            float g0 = sG[j0], g1 = sG[j1], bb0 = sBb[j0], bb1 = sBb[j1];
            l0[t] = make_float2((h0[lane * 33 + j0] - m0) * r0 * g0 + bb0,
                                (h0[lane * 33 + j1] - m0) * r0 * g1 + bb1);
            l1[t] = make_float2((h1[lane * 33 + j0] - m1) * r1 * g0 + bb0,
                                (h1[lane * 33 + j1] - m1) * r1 * g1 + bb1);
        }
    }

    float2 out0[16], out1[16];
    #pragma unroll
    for (int t = 0; t < 16; t++) {
        float2 bv = *reinterpret_cast<const float2*>(sB2 + 2 * t);
        out0[t] = bv; out1[t] = bv;
    }

    // hidden loop over DIM=256, two d per iteration (software pipelined)
    for (int d = 0; d < 256; d += 2) {
        float2 bias2 = *reinterpret_cast<const float2*>(sB1 + d);
        const float4* wA = reinterpret_cast<const float4*>(sW1 + d * 32);
        const float4* wB = reinterpret_cast<const float4*>(sW1 + d * 32 + 32);

        // 8 independent accumulator chains (2 d x 2 elem x 2 sub)
        float2 pA0 = make_float2(bias2.x, 0.f), pA0b = make_float2(0.f, 0.f);
        float2 pA1 = make_float2(bias2.x, 0.f), pA1b = make_float2(0.f, 0.f);
        float2 pB0 = make_float2(bias2.y, 0.f), pB0b = make_float2(0.f, 0.f);
        float2 pB1 = make_float2(bias2.y, 0.f), pB1b = make_float2(0.f, 0.f);
        #pragma unroll
        for (int qq = 0; qq < 8; qq++) {
            float4 wa = wA[qq];
            float4 wb = wB[qq];
            float2 waxy = make_float2(wa.x, wa.y), wazw = make_float2(wa.z, wa.w);
            float2 wbxy = make_float2(wb.x, wb.y), wbzw = make_float2(wb.z, wb.w);
            pA0  = ffma2(l0[2 * qq],     waxy, pA0);
            pA0b = ffma2(l0[2 * qq + 1], wazw, pA0b);
            pA1  = ffma2(l1[2 * qq],     waxy, pA1);
            pA1b = ffma2(l1[2 * qq + 1], wazw, pA1b);
            pB0  = ffma2(l0[2 * qq],     wbxy, pB0);
            pB0b = ffma2(l0[2 * qq + 1], wbzw, pB0b);
            pB1  = ffma2(l1[2 * qq],     wbxy, pB1);
            pB1b = ffma2(l1[2 * qq + 1], wbzw, pB1b);
        }

        // 4 independent horizontal + hswish chains (1/6 folded into w2T)
        float2 sA0 = fadd2(pA0, pA0b);
        float2 sA1 = fadd2(pA1, pA1b);
        float2 sB0 = fadd2(pB0, pB0b);
        float2 sB1v = fadd2(pB1, pB1b);
        float vA0 = sA0.x + sA0.y;
        float vA1 = sA1.x + sA1.y;
        float vB0 = sB0.x + sB0.y;
        float vB1 = sB1v.x + sB1v.y;
        float hA0 = vA0 * fminf(fmaxf(vA0 + 3.0f, 0.0f), 6.0f);
        float hA1 = vA1 * fminf(fmaxf(vA1 + 3.0f, 0.0f), 6.0f);
        float hB0 = vB0 * fminf(fmaxf(vB0 + 3.0f, 0.0f), 6.0f);
        float hB1 = vB1 * fminf(fmaxf(vB1 + 3.0f, 0.0f), 6.0f);
        float2 hpA0 = make_float2(hA0, hA0), hpA1 = make_float2(hA1, hA1);
        float2 hpB0 = make_float2(hB0, hB0), hpB1 = make_float2(hB1, hB1);

        const float4* w2A = reinterpret_cast<const float4*>(sW2T + d * 36);
        const float4* w2B = reinterpret_cast<const float4*>(sW2T + d * 36 + 36);
        #pragma unroll
        for (int qq = 0; qq < 8; qq++) {
            float4 wa = w2A[qq];
            float4 wb = w2B[qq];
            float2 waxy = make_float2(wa.x, wa.y), wazw = make_float2(wa.z, wa.w);
            float2 wbxy = make_float2(wb.x, wb.y), wbzw = make_float2(wb.z, wb.w);
            out0[2 * qq]     = ffma2(hpA0, waxy, out0[2 * qq]);
            out0[2 * qq + 1] = ffma2(hpA0, wazw, out0[2 * qq + 1]);
            out1[2 * qq]     = ffma2(hpA1, waxy, out1[2 * qq]);
            out1[2 * qq + 1] = ffma2(hpA1, wazw, out1[2 * qq + 1]);
            out0[2 * qq]     = ffma2(hpB0, wbxy, out0[2 * qq]);
            out0[2 * qq + 1] = ffma2(hpB0, wbzw, out0[2 * qq + 1]);
            out1[2 * qq]     = ffma2(hpB1, wbxy, out1[2 * qq]);
            out1[2 * qq + 1] = ffma2(hpB1, wbzw, out1[2 * qq + 1]);
        }
    }

    if (TOKEN) {
        #pragma unroll
        for (int t = 0; t < 16; t++) {
            h0[(2 * t) * 33 + lane]     += out0[t].x;
            h0[(2 * t + 1) * 33 + lane] += out0[t].y;
            h1[(2 * t) * 33 + lane]     += out1[t].x;
            h1[(2 * t + 1) * 33 + lane] += out1[t].y;
        }
    } else {
        #pragma unroll
        for (int t = 0; t < 16; t++) {
            h0[lane * 33 + 2 * t]     += out0[t].x;
            h0[lane * 33 + 2 * t + 1] += out0[t].y;
            h1[lane * 33 + 2 * t]     += out1[t].x;
            h1[lane * 33 + 2 * t + 1] += out1[t].y;
        }
    }
    __syncwarp();
}

extern __shared__ float smem[];

__global__ __launch_bounds__(256, 1)
void mixer_kernel(
    const float* __restrict__ x,
    const float* __restrict__ conv_w, const float* __restrict__ conv_b,
    const float* __restrict__ fc0_w,  const float* __restrict__ fc0_b,
    const float* __restrict__ ln1_g,  const float* __restrict__ ln1_b,
    const float* __restrict__ w11,    const float* __restrict__ b11,
    const float* __restrict__ w12,    const float* __restrict__ b12,
    const float* __restrict__ ln2_g,  const float* __restrict__ ln2_b,
    const float* __restrict__ w21,    const float* __restrict__ b21,
    const float* __restrict__ w22,    const float* __restrict__ b22,
    const float* __restrict__ fc1_w,  const float* __restrict__ fc1_b,
    const float* __restrict__ fcout_w,const float* __restrict__ fcout_b,
    float* __restrict__ out, int B)
{
    const int tid = threadIdx.x;
    const int lane = tid & 31;
    const int wid = tid >> 5;

    float* sW11  = smem + OFF_W11;
    float* sW12T = smem + OFF_W12T;
    float* sW21  = smem + OFF_W21;
    float* sW22T = smem + OFF_W22T;
    float* sB11  = smem + OFF_B11;
    float* sB12  = smem + OFF_B12;
    float* sB21  = smem + OFF_B21;
    float* sB22  = smem + OFF_B22;
    float* sLn1g = smem + OFF_LN1G;
    float* sLn1b = smem + OFF_LN1B;
    float* sLn2g = smem + OFF_LN2G;
    float* sLn2b = smem + OFF_LN2B;
    float* sH    = smem + OFF_H;
    float* sStats= smem + OFF_STATS;

    const int e0 = blockIdx.x * 16 + wid * 2;
    const int e1 = e0 + 1;
    const bool act0 = (e0 < B), act1 = (e1 < B);
    float* h0 = sH + (wid * 2) * 1056;
    float* h1 = h0 + 1056;
    float* st0 = sStats + wid * 128;
    float* st1 = st0 + 64;

    // ---- stage fc0 weights, then preprocess (conv1x1 + fc0) ----
    for (int i = tid; i < 1024; i += 256) sW11[i] = fc0_w[i];
    if (tid < 32) sB11[tid] = fc0_b[tid];
    __syncthreads();

    {
        const float cw0 = conv_w[0], cw1 = conv_w[1], cw2 = conv_w[2];
        const float cb  = conv_b[0];
        #pragma unroll
        for (int e = 0; e < 2; e++) {
            const int eb = e0 + e;
            if (eb >= B) break;
            float* hh = e ? h1 : h0;
            const float* xb = x + (size_t)eb * 3072 + lane * 32;
            float2 gp[16];
            #pragma unroll
            for (int q = 0; q < 8; q++) {
                float4 v0 = *reinterpret_cast<const float4*>(xb + q * 4);
                float4 v1 = *reinterpret_cast<const float4*>(xb + 1024 + q * 4);
                float4 v2 = *reinterpret_cast<const float4*>(xb + 2048 + q * 4);
                float g0 = cw0 * v0.x + cw1 * v1.x + cw2 * v2.x + cb;
                float g1 = cw0 * v0.y + cw1 * v1.y + cw2 * v2.y + cb;
                float g2 = cw0 * v0.z + cw1 * v1.z + cw2 * v2.z + cb;
                float g3 = cw0 * v0.w + cw1 * v1.w + cw2 * v2.w + cb;
                gp[2 * q]     = make_float2(g0, g1);
                gp[2 * q + 1] = make_float2(g2, g3);
            }
            for (int j = 0; j < 32; j++) {
                const float4* wq = reinterpret_cast<const float4*>(sW11 + j * 32);
                float2 acc = make_float2(0.f, 0.f), accb = make_float2(0.f, 0.f);
                #pragma unroll
                for (int q = 0; q < 8; q++) {
                    float4 w = wq[q];
                    acc  = ffma2(gp[2 * q],     make_float2(w.x, w.y), acc);
                    accb = ffma2(gp[2 * q + 1], make_float2(w.z, w.w), accb);
                }
                float2 sv = fadd2(acc, accb);
                hh[lane * 33 + j] = sv.x + sv.y + sB11[j];
            }
        }
    }
    __syncthreads();

    // ---- 8 layers x 2 repeats ----
    for (int l = 0; l < 8; l++) {
        // stage this layer's weights (w12/w22 transposed to [256][36], /6)
        {
            const float4* s1 = reinterpret_cast<const float4*>(w11 + l * 8192);
            float4* d1 = reinterpret_cast<float4*>(sW11);
            for (int i = tid; i < 2048; i += 256) d1[i] = s1[i];
            const float4* s2 = reinterpret_cast<const float4*>(w21 + l * 8192);
            float4* d2 = reinterpret_cast<float4*>(sW21);
            for (int i = tid; i < 2048; i += 256) d2[i] = s2[i];
            const float* g12 = w12 + l * 8192;
            for (int i = tid; i < 8192; i += 256) {
                int d = i & 255, k = i >> 8;
                sW12T[d * 36 + k] = g12[i] * (1.0f / 6.0f);
            }
            const float* g22 = w22 + l * 8192;
            for (int i = tid; i < 8192; i += 256) {
                int d = i & 255, k = i >> 8;
                sW22T[d * 36 + k] = g22[i] * (1.0f / 6.0f);
            }
            if (tid < 256) { sB11[tid] = b11[l * 256 + tid]; sB21[tid] = b21[l * 256 + tid]; }
            if (tid < 32) {
                sB12[tid]  = b12[l * 32 + tid];
                sB22[tid]  = b22[l * 32 + tid];
                sLn1g[tid] = ln1_g[l * 32 + tid];
                sLn1b[tid] = ln1_b[l * 32 + tid];
                sLn2g[tid] = ln2_g[l * 32 + tid];
                sLn2b[tid] = ln2_b[l * 32 + tid];
            }
        }
        __syncthreads();

        for (int rep = 0; rep < 2; rep++) {
            mix_branch<true >(h0, h1, sW11, sW12T, sB11, sB12, sLn1g, sLn1b, st0, st1, lane);
            mix_branch<false>(h0, h1, sW21, sW22T, sB21, sB22, sLn2g, sLn2b, st0, st1, lane);
        }
        __syncthreads();
    }

    // ---- head: fc1 + hardswish + avgpool(32) + fcout ----
    {
        const float4* s1 = reinterpret_cast<const float4*>(fc1_w);
        float4* d1 = reinterpret_cast<float4*>(sW11);
        for (int i = tid; i < 1024; i += 256) d1[i] = s1[i];
        for (int i = tid; i < 1280; i += 256) sW21[i] = fcout_w[i];
        if (tid < 128) sB11[tid] = fc1_b[tid];
        if (tid < 10)  sB12[tid] = fcout_b[tid];
    }
    __syncthreads();

    #pragma unroll
    for (int e = 0; e < 2; e++) {
        const bool act = e ? act1 : act0;
        if (!act) break;
        float* hh = e ? h1 : h0;
        float2 ap[16];
        #pragma unroll
        for (int t = 0; t < 16; t++)
            ap[t] = make_float2(hh[lane * 33 + 2 * t], hh[lane * 33 + 2 * t + 1]);
        float pool[4] = {0.f, 0.f, 0.f, 0.f};
        for (int d = 0; d < 128; d++) {
            const float4* wq = reinterpret_cast<const float4*>(sW11 + d * 32);
            float2 acc = make_float2(0.f, 0.f), accb = make_float2(0.f, 0.f);
            #pragma unroll
            for (int q = 0; q < 8; q++) {
                float4 w = wq[q];
                acc  = ffma2(ap[2 * q],     make_float2(w.x, w.y), acc);
                accb = ffma2(ap[2 * q + 1], make_float2(w.z, w.w), accb);
            }
            float2 sv = fadd2(acc, accb);
            float v = sv.x + sv.y + sB11[d];
            float y = v * fminf(fmaxf(v + 3.0f, 0.0f), 6.0f) * (1.0f / 6.0f);
            pool[d >> 5] += y;
        }
        #pragma unroll
        for (int p = 0; p < 4; p++) pool[p] *= (1.0f / 32.0f);
        const int eb = e ? e1 : e0;
        #pragma unroll
        for (int o = 0; o < 10; o++) {
            float4 wv = *reinterpret_cast<const float4*>(sW21 + o * 128 + lane * 4);
            float v = pool[0] * wv.x + pool[1] * wv.y + pool[2] * wv.z + pool[3] * wv.w;
            #pragma unroll
            for (int s = 16; s > 0; s >>= 1)
                v += __shfl_xor_sync(0xffffffffu, v, s);
            if (lane == 0) out[(size_t)eb * 10 + o] = v + sB12[o];
        }
    }
}

extern "C" void kernel_launch(void* const* d_in, const int* in_sizes, int n_in,
                              void* d_out, int out_size) {
    const float* x       = (const float*)d_in[0];
    const float* conv_w  = (const float*)d_in[1];
    const float* conv_b  = (const float*)d_in[2];
    const float* fc0_w   = (const float*)d_in[3];
    const float* fc0_b   = (const float*)d_in[4];
    const float* ln1_g   = (const float*)d_in[5];
    const float* ln1_b   = (const float*)d_in[6];
    const float* w11     = (const float*)d_in[7];
    const float* b11     = (const float*)d_in[8];
    const float* w12     = (const float*)d_in[9];
    const float* b12     = (const float*)d_in[10];
    const float* ln2_g   = (const float*)d_in[11];
    const float* ln2_b   = (const float*)d_in[12];
    const float* w21     = (const float*)d_in[13];
    const float* b21     = (const float*)d_in[14];
    const float* w22     = (const float*)d_in[15];
    const float* b22     = (const float*)d_in[16];
    const float* fc1_w   = (const float*)d_in[17];
    const float* fc1_b   = (const float*)d_in[18];
    const float* fcout_w = (const float*)d_in[19];
    const float* fcout_b = (const float*)d_in[20];
    float* out = (float*)d_out;

    const int B = in_sizes[0] / 3072;   // 3*32*32 floats per element
    const int blocks = (B + 15) / 16;
    const size_t smem_bytes = (size_t)SMEM_FLOATS * sizeof(float);

    cudaFuncSetAttribute(mixer_kernel,
                         cudaFuncAttributeMaxDynamicSharedMemorySize,
                         (int)smem_bytes);
    mixer_kernel<<<blocks, 256, smem_bytes>>>(
        x, conv_w, conv_b, fc0_w, fc0_b, ln1_g, ln1_b,
        w11, b11, w12, b12, ln2_g, ln2_b, w21, b21, w22, b22,
        fc1_w, fc1_b, fcout_w, fcout_b, out, B);
}